// round 1
// baseline (speedup 1.0000x reference)
#include <cuda_runtime.h>
#include <math.h>

#define N_NODES_MAX 100000
#define HID 128
#define NF 128
#define NG 50
#define EPB 8

// Scratch (static device allocations are the sanctioned scratch mechanism)
__device__ float g_x[(size_t)N_NODES_MAX * HID];
__device__ float g_agg[(size_t)N_NODES_MAX * HID];

__device__ __forceinline__ float sspf(float v) {
    // softplus(v) - ln(2)
    float sp = (v > 20.0f) ? v : __logf(1.0f + __expf(v));
    return sp - 0.69314718056f;
}

// C = act(A @ W + bias), A:[n,128], W:[128,128] row-major (fan_in, fan_out)
__global__ __launch_bounds__(256) void gemm128_kernel(
    const float* __restrict__ A, const float* __restrict__ W,
    const float* __restrict__ bias, float* __restrict__ C,
    int n, int act)
{
    extern __shared__ float s[];
    float* ws = s;                 // 128*128
    float* as = s + 128 * 128;     // 8*132 (padded)
    int tid = threadIdx.x;

    for (int i = tid * 4; i < 128 * 128; i += 256 * 4)
        *(float4*)&ws[i] = *(const float4*)&W[i];

    int wi = tid >> 5;   // warp -> row within tile
    int la = tid & 31;   // lane -> 4-col chunk
    float4 bb = make_float4(0.f, 0.f, 0.f, 0.f);
    if (bias) bb = *(const float4*)&bias[la * 4];
    __syncthreads();

    for (int rb = blockIdx.x * 8; rb < n; rb += gridDim.x * 8) {
        int rows = min(8, n - rb);
        if (wi < rows)
            *(float4*)&as[wi * 132 + la * 4] =
                *(const float4*)&A[(size_t)(rb + wi) * HID + la * 4];
        __syncthreads();

        float4 acc = bb;
        const float* ar = &as[wi * 132];
        #pragma unroll 8
        for (int k = 0; k < 128; k++) {
            float av = ar[k];
            float4 wv = *(const float4*)&ws[k * 128 + la * 4];
            acc.x = fmaf(av, wv.x, acc.x);
            acc.y = fmaf(av, wv.y, acc.y);
            acc.z = fmaf(av, wv.z, acc.z);
            acc.w = fmaf(av, wv.w, acc.w);
        }
        if (act) {
            acc.x = sspf(acc.x); acc.y = sspf(acc.y);
            acc.z = sspf(acc.z); acc.w = sspf(acc.w);
        }
        if (wi < rows)
            *(float4*)&C[(size_t)(rb + wi) * HID + la * 4] = acc;
        __syncthreads();
    }
}

__global__ __launch_bounds__(256) void zero_kernel(float* __restrict__ p, size_t n4)
{
    size_t i = (size_t)blockIdx.x * blockDim.x + threadIdx.x;
    size_t stride = (size_t)gridDim.x * blockDim.x;
    float4 z = make_float4(0.f, 0.f, 0.f, 0.f);
    for (; i < n4; i += stride)
        ((float4*)p)[i] = z;
}

// Per-edge: d -> gaussian smearing -> MLP(50->128 ssp ->128) -> *cutoff ->
// msg = x[col]*W -> atomicAdd into agg[row]. Thread = filter index, 8 edges/iter.
__global__ __launch_bounds__(128, 3) void edge_kernel(
    const float* __restrict__ pos, const int* __restrict__ ei,
    const float* __restrict__ w1, const float* __restrict__ b1,
    const float* __restrict__ w2, const float* __restrict__ b2,
    const float* __restrict__ x, float* __restrict__ agg, int E)
{
    extern __shared__ float s[];
    float* w2t  = s;                    // [128][132] transposed, padded
    float* eas  = w2t + 128 * 132;      // [EPB][52]  (50 gaussians + 2 zero pad)
    float* hids = eas + EPB * 52;       // [EPB][128]
    float* ds   = hids + EPB * 128;     // [EPB]
    float* cw   = ds + EPB;             // [EPB] cosine cutoff
    int* rows_  = (int*)(cw + EPB);     // [EPB]
    int* cols_  = rows_ + EPB;          // [EPB]

    int tid = threadIdx.x;

    // w2 transposed into smem: w2t[o][k] = w2[k][o]; per-thread contiguous k.
    #pragma unroll 4
    for (int k = 0; k < 128; k++)
        w2t[tid * 132 + k] = w2[k * 128 + tid];

    // w1 column for this thread's filter lives in registers.
    float w1r[52];
    #pragma unroll
    for (int g = 0; g < NG; g++) w1r[g] = w1[g * 128 + tid];
    w1r[50] = 0.f; w1r[51] = 0.f;
    float b1r = b1[tid];
    float b2r = b2[tid];

    const float step  = 10.0f / 49.0f;
    const float coeff = -0.5f / (step * step);
    __syncthreads();

    for (int base = blockIdx.x * EPB; base < E; base += gridDim.x * EPB) {
        int ne = min(EPB, E - base);

        if (tid < ne) {
            int r = ei[base + tid];
            int c = ei[E + base + tid];
            rows_[tid] = r; cols_[tid] = c;
            float dx = pos[3 * r + 0] - pos[3 * c + 0];
            float dy = pos[3 * r + 1] - pos[3 * c + 1];
            float dz = pos[3 * r + 2] - pos[3 * c + 2];
            float d = sqrtf(dx * dx + dy * dy + dz * dz);
            ds[tid] = d;
            cw[tid] = 0.5f * (__cosf(d * 0.314159265358979f) + 1.0f);
        }
        __syncthreads();

        // Gaussian smearing into smem (padded to 52, pad = 0)
        for (int i = tid; i < ne * 52; i += 128) {
            int el = i / 52;
            int g  = i - el * 52;
            float diff = ds[el] - (float)g * step;
            eas[i] = (g < NG) ? __expf(coeff * diff * diff) : 0.f;
        }
        __syncthreads();

        // Prefetch gathered source features (coalesced 512B per edge; L2-hot)
        float xv[EPB];
        #pragma unroll
        for (int el = 0; el < EPB; el++)
            xv[el] = (el < ne) ? x[(size_t)cols_[el] * NF + tid] : 0.f;

        // Layer 1: hid[t] = ssp(sum_g ea[g] * w1[g][t] + b1[t])
        float acc[EPB];
        #pragma unroll
        for (int el = 0; el < EPB; el++) acc[el] = b1r;
        #pragma unroll
        for (int g = 0; g < 52; g += 4) {
            #pragma unroll
            for (int el = 0; el < EPB; el++) {
                float4 e4 = *(const float4*)&eas[el * 52 + g];  // broadcast
                acc[el] = fmaf(e4.x, w1r[g + 0], acc[el]);
                acc[el] = fmaf(e4.y, w1r[g + 1], acc[el]);
                acc[el] = fmaf(e4.z, w1r[g + 2], acc[el]);
                acc[el] = fmaf(e4.w, w1r[g + 3], acc[el]);
            }
        }
        #pragma unroll
        for (int el = 0; el < EPB; el++)
            hids[el * 128 + tid] = sspf(acc[el]);
        __syncthreads();

        // Layer 2: W[t] = sum_k hid[k] * w2[k][t] + b2[t]
        float acc2[EPB];
        #pragma unroll
        for (int el = 0; el < EPB; el++) acc2[el] = b2r;
        #pragma unroll 8
        for (int k = 0; k < 128; k += 4) {
            float4 w4 = *(const float4*)&w2t[tid * 132 + k];    // conflict-free .128
            #pragma unroll
            for (int el = 0; el < EPB; el++) {
                float4 h4 = *(const float4*)&hids[el * 128 + k]; // broadcast
                acc2[el] = fmaf(h4.x, w4.x, acc2[el]);
                acc2[el] = fmaf(h4.y, w4.y, acc2[el]);
                acc2[el] = fmaf(h4.z, w4.z, acc2[el]);
                acc2[el] = fmaf(h4.w, w4.w, acc2[el]);
            }
        }

        // Cutoff, modulate gathered features, scatter-add
        #pragma unroll
        for (int el = 0; el < EPB; el++) {
            if (el < ne) {
                float Wv = acc2[el] * cw[el];
                atomicAdd(&agg[(size_t)rows_[el] * NF + tid], xv[el] * Wv);
            }
        }
        __syncthreads();
    }
}

extern "C" void kernel_launch(void* const* d_in, const int* in_sizes, int n_in,
                              void* d_out, int out_size)
{
    const float* h      = (const float*)d_in[0];
    const float* pos    = (const float*)d_in[1];
    const int*   ei     = (const int*)d_in[2];
    const float* mlp_w1 = (const float*)d_in[3];
    const float* mlp_b1 = (const float*)d_in[4];
    const float* mlp_w2 = (const float*)d_in[5];
    const float* mlp_b2 = (const float*)d_in[6];
    const float* lin1_w = (const float*)d_in[7];
    const float* lin2_w = (const float*)d_in[8];
    const float* lin2_b = (const float*)d_in[9];
    const float* lin_w  = (const float*)d_in[10];
    const float* lin_b  = (const float*)d_in[11];
    float* out = (float*)d_out;

    int N = in_sizes[0] / HID;
    int E = in_sizes[2] / 2;

    float *xbuf, *aggbuf;
    cudaGetSymbolAddress((void**)&xbuf, g_x);
    cudaGetSymbolAddress((void**)&aggbuf, g_agg);

    const int GEMM_SMEM = (128 * 128 + 8 * 132) * (int)sizeof(float);
    const int EDGE_SMEM = (128 * 132 + EPB * 52 + EPB * 128 + 2 * EPB) * (int)sizeof(float)
                          + 2 * EPB * (int)sizeof(int);
    cudaFuncSetAttribute(gemm128_kernel, cudaFuncAttributeMaxDynamicSharedMemorySize, GEMM_SMEM);
    cudaFuncSetAttribute(edge_kernel,   cudaFuncAttributeMaxDynamicSharedMemorySize, EDGE_SMEM);

    const int GRID = 444;  // ~3 CTAs per SM, persistent

    // x = h @ lin1_w
    gemm128_kernel<<<GRID, 256, GEMM_SMEM>>>(h, lin1_w, nullptr, xbuf, N, 0);
    // agg = 0
    zero_kernel<<<GRID, 256>>>(aggbuf, (size_t)N * NF / 4);
    // edge messages + scatter
    edge_kernel<<<GRID, 128, EDGE_SMEM>>>(pos, ei, mlp_w1, mlp_b1, mlp_w2, mlp_b2,
                                          xbuf, aggbuf, E);
    // x = ssp(agg @ lin2_w + lin2_b)
    gemm128_kernel<<<GRID, 256, GEMM_SMEM>>>(aggbuf, lin2_w, lin2_b, xbuf, N, 1);
    // out = x @ lin_w + lin_b
    gemm128_kernel<<<GRID, 256, GEMM_SMEM>>>(xbuf, lin_w, lin_b, out, N, 0);
}

// round 5
// speedup vs baseline: 2.3095x; 2.3095x over previous
#include <cuda_runtime.h>
#include <cstdint>
#include <math.h>

#define N_NODES_MAX 100000
#define HID 128
#define NF 128
#define NG 50

__device__ float g_x[(size_t)N_NODES_MAX * HID];
__device__ float g_agg[(size_t)N_NODES_MAX * HID];

__device__ __forceinline__ float sspf(float v) {
    float sp = (v > 20.0f) ? v : __logf(1.0f + __expf(v));
    return sp - 0.69314718056f;
}

__device__ __forceinline__ uint32_t f2tf(float f) {
    uint32_t u;
    asm("cvt.rna.tf32.f32 %0, %1;" : "=r"(u) : "f"(f));
    return u;
}

// D += A@B, m16n8k8 tf32, fp32 accumulate (baseline PTX, works on sm_100)
__device__ __forceinline__ void mma8(float* c, const uint32_t* a, const uint32_t* b) {
    asm volatile(
        "mma.sync.aligned.m16n8k8.row.col.f32.tf32.tf32.f32 "
        "{%0,%1,%2,%3}, {%4,%5,%6,%7}, {%8,%9}, {%0,%1,%2,%3};"
        : "+f"(c[0]), "+f"(c[1]), "+f"(c[2]), "+f"(c[3])
        : "r"(a[0]), "r"(a[1]), "r"(a[2]), "r"(a[3]), "r"(b[0]), "r"(b[1]));
}

__device__ __forceinline__ void red2(float* p, float a, float b) {
    asm volatile("red.global.add.v2.f32 [%0], {%1, %2};"
                 :: "l"(p), "f"(a), "f"(b) : "memory");
}

// ------------------- Edge MLP (tf32 mma.sync) -------------------
// Tile = 128 edges. 8 warps x 16 output filters each. Weights persistent in regs.
#define AS 60    // attr row stride (words): gi*28+ci -> conflict-free
#define HS 140   // hid row stride (words): gi*12+ci -> conflict-free

#define EO_ATTR 0
#define EO_HID  (128 * AS)                 // 7680
#define EO_ROWS (EO_HID + 128 * HS)        // 25600
#define EO_COLS (EO_ROWS + 128)
#define EO_CW   (EO_COLS + 128)
#define EO_D    (EO_CW + 128)
#define EO_B1   (EO_D + 128)
#define EO_B2   (EO_B1 + 128)
#define E_SMEM_WORDS (EO_B2 + 128)

__global__ __launch_bounds__(256, 1) void edge_mma_kernel(
    const float* __restrict__ pos, const int* __restrict__ ei,
    const float* __restrict__ w1, const float* __restrict__ b1,
    const float* __restrict__ w2, const float* __restrict__ b2,
    const float* __restrict__ x, float* __restrict__ agg, int E)
{
    extern __shared__ float s[];
    float* attrS = s + EO_ATTR;
    float* hidS  = s + EO_HID;
    int*   rowsS = (int*)(s + EO_ROWS);
    int*   colsS = (int*)(s + EO_COLS);
    float* cwS   = s + EO_CW;
    float* dS    = s + EO_D;
    float* b1sS  = s + EO_B1;
    float* b2sS  = s + EO_B2;

    const int tid = threadIdx.x;
    const int wid = tid >> 5, lane = tid & 31;
    const int gi = lane >> 2, ci = lane & 3;
    const int nbase = wid * 16;

    // Persistent B fragments (tf32) in registers.
    uint32_t b1u[7][2][2], b2u[16][2][2];
    #pragma unroll
    for (int kt = 0; kt < 7; kt++)
        #pragma unroll
        for (int nt = 0; nt < 2; nt++) {
            int n = nbase + nt * 8 + gi;
            int k0 = kt * 8 + ci;
            b1u[kt][nt][0] = f2tf((k0 < NG) ? w1[k0 * 128 + n] : 0.f);
            b1u[kt][nt][1] = f2tf((k0 + 4 < NG) ? w1[(k0 + 4) * 128 + n] : 0.f);
        }
    #pragma unroll
    for (int kt = 0; kt < 16; kt++)
        #pragma unroll
        for (int nt = 0; nt < 2; nt++) {
            int n = nbase + nt * 8 + gi;
            int k0 = kt * 8 + ci;
            b2u[kt][nt][0] = f2tf(w2[k0 * 128 + n]);
            b2u[kt][nt][1] = f2tf(w2[(k0 + 4) * 128 + n]);
        }
    if (tid < 128) { b1sS[tid] = b1[tid]; b2sS[tid] = b2[tid]; }
    __syncthreads();

    // per-warp bias regs
    float b1v[2][2], b2v[2][2];
    #pragma unroll
    for (int nt = 0; nt < 2; nt++) {
        int n0 = nbase + nt * 8 + 2 * ci;
        b1v[nt][0] = b1sS[n0]; b1v[nt][1] = b1sS[n0 + 1];
        b2v[nt][0] = b2sS[n0]; b2v[nt][1] = b2sS[n0 + 1];
    }

    const float step  = 10.0f / 49.0f;
    const float coeff = -0.5f / (step * step);

    for (int base = blockIdx.x * 128; base < E; base += gridDim.x * 128) {
        // ---- per-edge geometry ----
        if (tid < 128) {
            int e = base + tid;
            if (e < E) {
                int r = ei[e], c = ei[E + e];
                rowsS[tid] = r; colsS[tid] = c;
                float dx = pos[3 * r + 0] - pos[3 * c + 0];
                float dy = pos[3 * r + 1] - pos[3 * c + 1];
                float dz = pos[3 * r + 2] - pos[3 * c + 2];
                float d = sqrtf(dx * dx + dy * dy + dz * dz);
                dS[tid] = d;
                cwS[tid] = 0.5f * (__cosf(d * 0.314159265358979f) + 1.0f);
            } else {
                rowsS[tid] = 0; colsS[tid] = 0; dS[tid] = 0.f; cwS[tid] = 0.f;
            }
        }
        __syncthreads();

        // ---- Gaussian smearing: attr[128][56] (cols >= 50 zero) ----
        {
            int e = tid & 127, half = tid >> 7;
            float d = dS[e];
            #pragma unroll
            for (int j = 0; j < 28; j++) {
                int k = half * 28 + j;
                float diff = d - (float)k * step;
                attrS[e * AS + k] = (k < NG) ? __expf(coeff * diff * diff) : 0.f;
            }
        }
        __syncthreads();

        float acc[8][2][4];
        #pragma unroll
        for (int mt = 0; mt < 8; mt++)
            #pragma unroll
            for (int nt = 0; nt < 2; nt++)
                #pragma unroll
                for (int q = 0; q < 4; q++) acc[mt][nt][q] = 0.f;

        // ---- Layer 1: [128,56] @ [56,16] per warp ----
        #pragma unroll
        for (int kt = 0; kt < 7; kt++) {
            #pragma unroll
            for (int mt = 0; mt < 8; mt++) {
                int r = mt * 16 + gi;
                uint32_t a[4];
                a[0] = f2tf(attrS[r * AS + kt * 8 + ci]);
                a[1] = f2tf(attrS[(r + 8) * AS + kt * 8 + ci]);
                a[2] = f2tf(attrS[r * AS + kt * 8 + ci + 4]);
                a[3] = f2tf(attrS[(r + 8) * AS + kt * 8 + ci + 4]);
                mma8(acc[mt][0], a, b1u[kt][0]);
                mma8(acc[mt][1], a, b1u[kt][1]);
            }
        }

        // ---- bias + ssp -> hidS ----
        #pragma unroll
        for (int mt = 0; mt < 8; mt++) {
            int r = mt * 16 + gi;
            #pragma unroll
            for (int nt = 0; nt < 2; nt++) {
                int n0 = nbase + nt * 8 + 2 * ci;
                float2 v0, v1;
                v0.x = sspf(acc[mt][nt][0] + b1v[nt][0]);
                v0.y = sspf(acc[mt][nt][1] + b1v[nt][1]);
                v1.x = sspf(acc[mt][nt][2] + b1v[nt][0]);
                v1.y = sspf(acc[mt][nt][3] + b1v[nt][1]);
                *(float2*)&hidS[r * HS + n0] = v0;
                *(float2*)&hidS[(r + 8) * HS + n0] = v1;
            }
        }
        __syncthreads();

        #pragma unroll
        for (int mt = 0; mt < 8; mt++)
            #pragma unroll
            for (int nt = 0; nt < 2; nt++)
                #pragma unroll
                for (int q = 0; q < 4; q++) acc[mt][nt][q] = 0.f;

        // ---- Layer 2: [128,128] @ [128,16] per warp ----
        #pragma unroll 8
        for (int kt = 0; kt < 16; kt++) {
            #pragma unroll
            for (int mt = 0; mt < 8; mt++) {
                int r = mt * 16 + gi;
                uint32_t a[4];
                a[0] = f2tf(hidS[r * HS + kt * 8 + ci]);
                a[1] = f2tf(hidS[(r + 8) * HS + kt * 8 + ci]);
                a[2] = f2tf(hidS[r * HS + kt * 8 + ci + 4]);
                a[3] = f2tf(hidS[(r + 8) * HS + kt * 8 + ci + 4]);
                mma8(acc[mt][0], a, b2u[kt][0]);
                mma8(acc[mt][1], a, b2u[kt][1]);
            }
        }

        // ---- epilogue: bias, cutoff, gather x, scatter-add ----
        #pragma unroll
        for (int mt = 0; mt < 8; mt++) {
            int r0 = mt * 16 + gi, r1 = r0 + 8;
            float cw0 = cwS[r0], cw1 = cwS[r1];
            int gr0 = rowsS[r0], gc0 = colsS[r0];
            int gr1 = rowsS[r1], gc1 = colsS[r1];
            #pragma unroll
            for (int nt = 0; nt < 2; nt++) {
                int n0 = nbase + nt * 8 + 2 * ci;
                float wa = (acc[mt][nt][0] + b2v[nt][0]) * cw0;
                float wb = (acc[mt][nt][1] + b2v[nt][1]) * cw0;
                float wc = (acc[mt][nt][2] + b2v[nt][0]) * cw1;
                float wd = (acc[mt][nt][3] + b2v[nt][1]) * cw1;
                float2 x0 = *(const float2*)&x[(size_t)gc0 * 128 + n0];
                float2 x1 = *(const float2*)&x[(size_t)gc1 * 128 + n0];
                red2(&agg[(size_t)gr0 * 128 + n0], x0.x * wa, x0.y * wb);
                red2(&agg[(size_t)gr1 * 128 + n0], x1.x * wc, x1.y * wd);
            }
        }
        __syncthreads();
    }
}

// ------------------- Node GEMM (fp32, register-tiled) -------------------
__global__ __launch_bounds__(256) void gemm128_kernel(
    const float* __restrict__ A, const float* __restrict__ W,
    const float* __restrict__ bias, float* __restrict__ C,
    int n, int act)
{
    extern __shared__ float s[];
    float* ws = s;                  // 128*128
    float* as = s + 128 * 128;      // 64*132
    int tid = threadIdx.x, wid = tid >> 5, lane = tid & 31;

    for (int i = tid * 4; i < 128 * 128; i += 256 * 4)
        *(float4*)&ws[i] = *(const float4*)&W[i];
    float4 bb = make_float4(0.f, 0.f, 0.f, 0.f);
    if (bias) bb = *(const float4*)&bias[lane * 4];
    __syncthreads();

    for (int rb = blockIdx.x * 64; rb < n; rb += gridDim.x * 64) {
        for (int i = tid; i < 64 * 32; i += 256) {
            int r = i >> 5, c4 = i & 31;
            float4 v = make_float4(0.f, 0.f, 0.f, 0.f);
            if (rb + r < n) v = *(const float4*)&A[(size_t)(rb + r) * HID + c4 * 4];
            *(float4*)&as[r * 132 + c4 * 4] = v;
        }
        __syncthreads();

        float acc[8][4];
        #pragma unroll
        for (int j = 0; j < 8; j++) {
            acc[j][0] = bb.x; acc[j][1] = bb.y; acc[j][2] = bb.z; acc[j][3] = bb.w;
        }
        const float* ar = &as[wid * 8 * 132];
        #pragma unroll 4
        for (int k = 0; k < 128; k++) {
            float4 wv = *(const float4*)&ws[k * 128 + lane * 4];
            #pragma unroll
            for (int j = 0; j < 8; j++) {
                float av = ar[j * 132 + k];
                acc[j][0] = fmaf(av, wv.x, acc[j][0]);
                acc[j][1] = fmaf(av, wv.y, acc[j][1]);
                acc[j][2] = fmaf(av, wv.z, acc[j][2]);
                acc[j][3] = fmaf(av, wv.w, acc[j][3]);
            }
        }
        #pragma unroll
        for (int j = 0; j < 8; j++) {
            int r = rb + wid * 8 + j;
            if (r < n) {
                float4 o;
                o.x = acc[j][0]; o.y = acc[j][1]; o.z = acc[j][2]; o.w = acc[j][3];
                if (act) { o.x = sspf(o.x); o.y = sspf(o.y); o.z = sspf(o.z); o.w = sspf(o.w); }
                *(float4*)&C[(size_t)r * HID + lane * 4] = o;
            }
        }
        __syncthreads();
    }
}

__global__ __launch_bounds__(256) void zero_kernel(float* __restrict__ p, size_t n4)
{
    size_t i = (size_t)blockIdx.x * blockDim.x + threadIdx.x;
    size_t stride = (size_t)gridDim.x * blockDim.x;
    float4 z = make_float4(0.f, 0.f, 0.f, 0.f);
    for (; i < n4; i += stride) ((float4*)p)[i] = z;
}

extern "C" void kernel_launch(void* const* d_in, const int* in_sizes, int n_in,
                              void* d_out, int out_size)
{
    const float* h      = (const float*)d_in[0];
    const float* pos    = (const float*)d_in[1];
    const int*   ei     = (const int*)d_in[2];
    const float* mlp_w1 = (const float*)d_in[3];
    const float* mlp_b1 = (const float*)d_in[4];
    const float* mlp_w2 = (const float*)d_in[5];
    const float* mlp_b2 = (const float*)d_in[6];
    const float* lin1_w = (const float*)d_in[7];
    const float* lin2_w = (const float*)d_in[8];
    const float* lin2_b = (const float*)d_in[9];
    const float* lin_w  = (const float*)d_in[10];
    const float* lin_b  = (const float*)d_in[11];
    float* out = (float*)d_out;

    int N = in_sizes[0] / HID;
    int E = in_sizes[2] / 2;

    float *xbuf, *aggbuf;
    cudaGetSymbolAddress((void**)&xbuf, g_x);
    cudaGetSymbolAddress((void**)&aggbuf, g_agg);

    const int GEMM_SMEM = (128 * 128 + 64 * 132) * (int)sizeof(float);
    const int EDGE_SMEM = E_SMEM_WORDS * (int)sizeof(float);
    cudaFuncSetAttribute(gemm128_kernel, cudaFuncAttributeMaxDynamicSharedMemorySize, GEMM_SMEM);
    cudaFuncSetAttribute(edge_mma_kernel, cudaFuncAttributeMaxDynamicSharedMemorySize, EDGE_SMEM);

    const int GRID = 148;

    gemm128_kernel<<<GRID, 256, GEMM_SMEM>>>(h, lin1_w, nullptr, xbuf, N, 0);
    zero_kernel<<<GRID, 256>>>(aggbuf, (size_t)N * NF / 4);
    edge_mma_kernel<<<GRID, 256, EDGE_SMEM>>>(pos, ei, mlp_w1, mlp_b1, mlp_w2, mlp_b2,
                                              xbuf, aggbuf, E);
    gemm128_kernel<<<GRID, 256, GEMM_SMEM>>>(aggbuf, lin2_w, lin2_b, xbuf, N, 1);
    gemm128_kernel<<<GRID, 256, GEMM_SMEM>>>(xbuf, lin_w, lin_b, out, N, 0);
}

// round 6
// speedup vs baseline: 2.5941x; 1.1232x over previous
#include <cuda_runtime.h>
#include <cstdint>
#include <math.h>

#define N_NODES_MAX 100000
#define HID 128
#define NF 128
#define NG 50

__device__ float g_x[(size_t)N_NODES_MAX * HID];
__device__ float g_agg[(size_t)N_NODES_MAX * HID];

__device__ __forceinline__ float sspf(float v) {
    float sp = (v > 20.0f) ? v : __logf(1.0f + __expf(v));
    return sp - 0.69314718056f;
}

__device__ __forceinline__ uint32_t f2tf(float f) {
    uint32_t u;
    asm("cvt.rna.tf32.f32 %0, %1;" : "=r"(u) : "f"(f));
    return u;
}

// D += A@B, m16n8k8 tf32, fp32 accumulate (baseline PTX)
__device__ __forceinline__ void mma8(float* c, const uint32_t* a, const uint32_t* b) {
    asm volatile(
        "mma.sync.aligned.m16n8k8.row.col.f32.tf32.tf32.f32 "
        "{%0,%1,%2,%3}, {%4,%5,%6,%7}, {%8,%9}, {%0,%1,%2,%3};"
        : "+f"(c[0]), "+f"(c[1]), "+f"(c[2]), "+f"(c[3])
        : "r"(a[0]), "r"(a[1]), "r"(a[2]), "r"(a[3]), "r"(b[0]), "r"(b[1]));
}

__device__ __forceinline__ void red4(float* p, float a, float b, float c, float d) {
    asm volatile("red.global.add.v4.f32 [%0], {%1, %2, %3, %4};"
                 :: "l"(p), "f"(a), "f"(b), "f"(c), "f"(d) : "memory");
}

// ------------------- Edge MLP (tf32 mma.sync) -------------------
// Tile = 128 edges. 8 warps x 16 output filters each. Weights persistent in regs.
// attr/hid stored in smem as PRE-CONVERTED tf32 bits (no cvt on the load path).
#define AS 60    // attr row stride (words): (28*gi+ci) mod 32 all-distinct
#define HS 140   // hid row stride (words): (12*gi+ci) mod 32 all-distinct

#define EO_ATTR 0
#define EO_HID  (128 * AS)                 // 7680
#define EO_ROWS (EO_HID + 128 * HS)        // 25600
#define EO_COLS (EO_ROWS + 128)
#define EO_CW   (EO_COLS + 128)
#define EO_D    (EO_CW + 128)
#define EO_B1   (EO_D + 128)
#define EO_B2   (EO_B1 + 128)
#define E_SMEM_WORDS (EO_B2 + 128)

__global__ __launch_bounds__(256, 1) void edge_mma_kernel(
    const float* __restrict__ pos, const int* __restrict__ ei,
    const float* __restrict__ w1, const float* __restrict__ b1,
    const float* __restrict__ w2, const float* __restrict__ b2,
    const float* __restrict__ x, float* __restrict__ agg, int E)
{
    extern __shared__ float s[];
    uint32_t* attrT = (uint32_t*)(s + EO_ATTR);   // tf32 bits
    uint32_t* hidT  = (uint32_t*)(s + EO_HID);    // tf32 bits
    int*   rowsS = (int*)(s + EO_ROWS);
    int*   colsS = (int*)(s + EO_COLS);
    float* cwS   = s + EO_CW;
    float* dS    = s + EO_D;
    float* b1sS  = s + EO_B1;
    float* b2sS  = s + EO_B2;

    const int tid = threadIdx.x;
    const int wid = tid >> 5, lane = tid & 31;
    const int gi = lane >> 2, ci = lane & 3;
    const int nbase = wid * 16;

    // Persistent B fragments (tf32) in registers.
    uint32_t b1u[7][2][2], b2u[16][2][2];
    #pragma unroll
    for (int kt = 0; kt < 7; kt++)
        #pragma unroll
        for (int nt = 0; nt < 2; nt++) {
            int n = nbase + nt * 8 + gi;
            int k0 = kt * 8 + ci;
            b1u[kt][nt][0] = f2tf((k0 < NG) ? w1[k0 * 128 + n] : 0.f);
            b1u[kt][nt][1] = f2tf((k0 + 4 < NG) ? w1[(k0 + 4) * 128 + n] : 0.f);
        }
    #pragma unroll
    for (int kt = 0; kt < 16; kt++)
        #pragma unroll
        for (int nt = 0; nt < 2; nt++) {
            int n = nbase + nt * 8 + gi;
            int k0 = kt * 8 + ci;
            b2u[kt][nt][0] = f2tf(w2[k0 * 128 + n]);
            b2u[kt][nt][1] = f2tf(w2[(k0 + 4) * 128 + n]);
        }
    if (tid < 128) { b1sS[tid] = b1[tid]; b2sS[tid] = b2[tid]; }
    __syncthreads();

    // per-warp bias regs
    float b1v[2][2], b2v[2][2];
    #pragma unroll
    for (int nt = 0; nt < 2; nt++) {
        int n0 = nbase + nt * 8 + 2 * ci;
        b1v[nt][0] = b1sS[n0]; b1v[nt][1] = b1sS[n0 + 1];
        b2v[nt][0] = b2sS[n0]; b2v[nt][1] = b2sS[n0 + 1];
    }

    const float step  = 10.0f / 49.0f;
    const float coeff = -0.5f / (step * step);

    for (int base = blockIdx.x * 128; base < E; base += gridDim.x * 128) {
        // ---- per-edge geometry ----
        if (tid < 128) {
            int e = base + tid;
            if (e < E) {
                int r = ei[e], c = ei[E + e];
                rowsS[tid] = r; colsS[tid] = c;
                float dx = pos[3 * r + 0] - pos[3 * c + 0];
                float dy = pos[3 * r + 1] - pos[3 * c + 1];
                float dz = pos[3 * r + 2] - pos[3 * c + 2];
                float d = sqrtf(dx * dx + dy * dy + dz * dz);
                dS[tid] = d;
                cwS[tid] = 0.5f * (__cosf(d * 0.314159265358979f) + 1.0f);
            } else {
                rowsS[tid] = 0; colsS[tid] = 0; dS[tid] = 0.f; cwS[tid] = 0.f;
            }
        }
        __syncthreads();

        // ---- Gaussian smearing -> tf32 bits: attr[128][56] (cols >= 50 zero) ----
        {
            int e = tid & 127, half = tid >> 7;
            float d = dS[e];
            #pragma unroll
            for (int j = 0; j < 28; j++) {
                int k = half * 28 + j;
                float diff = d - (float)k * step;
                attrT[e * AS + k] = f2tf((k < NG) ? __expf(coeff * diff * diff) : 0.f);
            }
        }
        __syncthreads();

        float acc[8][2][4];
        #pragma unroll
        for (int mt = 0; mt < 8; mt++)
            #pragma unroll
            for (int nt = 0; nt < 2; nt++)
                #pragma unroll
                for (int q = 0; q < 4; q++) acc[mt][nt][q] = 0.f;

        // ---- Layer 1: [128,56] @ [56,16] per warp ----
        #pragma unroll
        for (int kt = 0; kt < 7; kt++) {
            #pragma unroll
            for (int mt = 0; mt < 8; mt++) {
                int r = mt * 16 + gi;
                uint32_t a[4];
                a[0] = attrT[r * AS + kt * 8 + ci];
                a[1] = attrT[(r + 8) * AS + kt * 8 + ci];
                a[2] = attrT[r * AS + kt * 8 + ci + 4];
                a[3] = attrT[(r + 8) * AS + kt * 8 + ci + 4];
                mma8(acc[mt][0], a, b1u[kt][0]);
                mma8(acc[mt][1], a, b1u[kt][1]);
            }
        }

        // ---- bias + ssp -> hid tf32 bits ----
        #pragma unroll
        for (int mt = 0; mt < 8; mt++) {
            int r = mt * 16 + gi;
            #pragma unroll
            for (int nt = 0; nt < 2; nt++) {
                int n0 = nbase + nt * 8 + 2 * ci;
                uint2 v0, v1;
                v0.x = f2tf(sspf(acc[mt][nt][0] + b1v[nt][0]));
                v0.y = f2tf(sspf(acc[mt][nt][1] + b1v[nt][1]));
                v1.x = f2tf(sspf(acc[mt][nt][2] + b1v[nt][0]));
                v1.y = f2tf(sspf(acc[mt][nt][3] + b1v[nt][1]));
                *(uint2*)&hidT[r * HS + n0] = v0;
                *(uint2*)&hidT[(r + 8) * HS + n0] = v1;
            }
        }
        __syncthreads();

        #pragma unroll
        for (int mt = 0; mt < 8; mt++)
            #pragma unroll
            for (int nt = 0; nt < 2; nt++)
                #pragma unroll
                for (int q = 0; q < 4; q++) acc[mt][nt][q] = 0.f;

        // ---- Layer 2: [128,128] @ [128,16] per warp ----
        #pragma unroll
        for (int kt = 0; kt < 16; kt++) {
            #pragma unroll
            for (int mt = 0; mt < 8; mt++) {
                int r = mt * 16 + gi;
                uint32_t a[4];
                a[0] = hidT[r * HS + kt * 8 + ci];
                a[1] = hidT[(r + 8) * HS + kt * 8 + ci];
                a[2] = hidT[r * HS + kt * 8 + ci + 4];
                a[3] = hidT[(r + 8) * HS + kt * 8 + ci + 4];
                mma8(acc[mt][0], a, b2u[kt][0]);
                mma8(acc[mt][1], a, b2u[kt][1]);
            }
        }

        // ---- epilogue: bias, cutoff, pair-shuffle -> float4 gather + red.v4 ----
        {
            const int odd = ci & 1;
            #pragma unroll
            for (int mt = 0; mt < 8; mt++) {
                int r0 = mt * 16 + gi, r1 = r0 + 8;
                float cw0 = cwS[r0], cw1 = cwS[r1];
                int mr = odd ? r1 : r0;
                int gr = rowsS[mr], gc = colsS[mr];
                #pragma unroll
                for (int nt = 0; nt < 2; nt++) {
                    float wa = (acc[mt][nt][0] + b2v[nt][0]) * cw0;
                    float wb = (acc[mt][nt][1] + b2v[nt][1]) * cw0;
                    float wc = (acc[mt][nt][2] + b2v[nt][0]) * cw1;
                    float wd = (acc[mt][nt][3] + b2v[nt][1]) * cw1;
                    // lane pair (ci, ci^1): even keeps row r0, odd keeps row r1;
                    // exchange the halves each one doesn't keep.
                    float sx = odd ? wa : wc;
                    float sy = odd ? wb : wd;
                    float rx = __shfl_xor_sync(0xffffffffu, sx, 1);
                    float ry = __shfl_xor_sync(0xffffffffu, sy, 1);
                    float v0 = odd ? rx : wa;
                    float v1 = odd ? ry : wb;
                    float v2 = odd ? wc : rx;
                    float v3 = odd ? wd : ry;
                    int cb = nbase + nt * 8 + 4 * (ci >> 1);
                    float4 xv = *(const float4*)&x[(size_t)gc * 128 + cb];
                    red4(&agg[(size_t)gr * 128 + cb],
                         v0 * xv.x, v1 * xv.y, v2 * xv.z, v3 * xv.w);
                }
            }
        }
        __syncthreads();
    }
}

// ------------------- Node GEMM (fp32, register-tiled, 16 warps) -------------------
__global__ __launch_bounds__(512) void gemm128_kernel(
    const float* __restrict__ A, const float* __restrict__ W,
    const float* __restrict__ bias, float* __restrict__ C,
    int n, int act)
{
    extern __shared__ float s[];
    float* ws = s;                  // 128*128
    float* as = s + 128 * 128;      // 128*132
    int tid = threadIdx.x, wid = tid >> 5, lane = tid & 31;

    for (int i = tid * 4; i < 128 * 128; i += 512 * 4)
        *(float4*)&ws[i] = *(const float4*)&W[i];
    float4 bb = make_float4(0.f, 0.f, 0.f, 0.f);
    if (bias) bb = *(const float4*)&bias[lane * 4];
    __syncthreads();

    for (int rb = blockIdx.x * 128; rb < n; rb += gridDim.x * 128) {
        for (int i = tid; i < 128 * 32; i += 512) {
            int r = i >> 5, c4 = i & 31;
            float4 v = make_float4(0.f, 0.f, 0.f, 0.f);
            if (rb + r < n) v = *(const float4*)&A[(size_t)(rb + r) * HID + c4 * 4];
            *(float4*)&as[r * 132 + c4 * 4] = v;
        }
        __syncthreads();

        float acc[8][4];
        #pragma unroll
        for (int j = 0; j < 8; j++) {
            acc[j][0] = bb.x; acc[j][1] = bb.y; acc[j][2] = bb.z; acc[j][3] = bb.w;
        }
        const float* ar = &as[wid * 8 * 132];
        #pragma unroll 4
        for (int k = 0; k < 128; k++) {
            float4 wv = *(const float4*)&ws[k * 128 + lane * 4];
            #pragma unroll
            for (int j = 0; j < 8; j++) {
                float av = ar[j * 132 + k];
                acc[j][0] = fmaf(av, wv.x, acc[j][0]);
                acc[j][1] = fmaf(av, wv.y, acc[j][1]);
                acc[j][2] = fmaf(av, wv.z, acc[j][2]);
                acc[j][3] = fmaf(av, wv.w, acc[j][3]);
            }
        }
        #pragma unroll
        for (int j = 0; j < 8; j++) {
            int r = rb + wid * 8 + j;
            if (r < n) {
                float4 o;
                o.x = acc[j][0]; o.y = acc[j][1]; o.z = acc[j][2]; o.w = acc[j][3];
                if (act) { o.x = sspf(o.x); o.y = sspf(o.y); o.z = sspf(o.z); o.w = sspf(o.w); }
                *(float4*)&C[(size_t)r * HID + lane * 4] = o;
            }
        }
        __syncthreads();
    }
}

__global__ __launch_bounds__(256) void zero_kernel(float* __restrict__ p, size_t n4)
{
    size_t i = (size_t)blockIdx.x * blockDim.x + threadIdx.x;
    size_t stride = (size_t)gridDim.x * blockDim.x;
    float4 z = make_float4(0.f, 0.f, 0.f, 0.f);
    for (; i < n4; i += stride) ((float4*)p)[i] = z;
}

extern "C" void kernel_launch(void* const* d_in, const int* in_sizes, int n_in,
                              void* d_out, int out_size)
{
    const float* h      = (const float*)d_in[0];
    const float* pos    = (const float*)d_in[1];
    const int*   ei     = (const int*)d_in[2];
    const float* mlp_w1 = (const float*)d_in[3];
    const float* mlp_b1 = (const float*)d_in[4];
    const float* mlp_w2 = (const float*)d_in[5];
    const float* mlp_b2 = (const float*)d_in[6];
    const float* lin1_w = (const float*)d_in[7];
    const float* lin2_w = (const float*)d_in[8];
    const float* lin2_b = (const float*)d_in[9];
    const float* lin_w  = (const float*)d_in[10];
    const float* lin_b  = (const float*)d_in[11];
    float* out = (float*)d_out;

    int N = in_sizes[0] / HID;
    int E = in_sizes[2] / 2;

    float *xbuf, *aggbuf;
    cudaGetSymbolAddress((void**)&xbuf, g_x);
    cudaGetSymbolAddress((void**)&aggbuf, g_agg);

    const int GEMM_SMEM = (128 * 128 + 128 * 132) * (int)sizeof(float);
    const int EDGE_SMEM = E_SMEM_WORDS * (int)sizeof(float);
    cudaFuncSetAttribute(gemm128_kernel, cudaFuncAttributeMaxDynamicSharedMemorySize, GEMM_SMEM);
    cudaFuncSetAttribute(edge_mma_kernel, cudaFuncAttributeMaxDynamicSharedMemorySize, EDGE_SMEM);

    const int GRID = 148;

    gemm128_kernel<<<GRID, 512, GEMM_SMEM>>>(h, lin1_w, nullptr, xbuf, N, 0);
    zero_kernel<<<GRID, 256>>>(aggbuf, (size_t)N * NF / 4);
    edge_mma_kernel<<<GRID, 256, EDGE_SMEM>>>(pos, ei, mlp_w1, mlp_b1, mlp_w2, mlp_b2,
                                              xbuf, aggbuf, E);
    gemm128_kernel<<<GRID, 512, GEMM_SMEM>>>(aggbuf, lin2_w, lin2_b, xbuf, N, 1);
    gemm128_kernel<<<GRID, 512, GEMM_SMEM>>>(xbuf, lin_w, lin_b, out, N, 0);
}